// round 1
// baseline (speedup 1.0000x reference)
#include <cuda_runtime.h>
#include <stdint.h>

// Problem shapes (from reference setup_inputs): N=50000, E=800000, F_IN=512, H=128, C=40.
// Scratch capacity sized to these; runtime dims derived from in_sizes.
#define N_CAP 50000
#define H_CAP 128
#define C_CAP 64

__device__ float g_dinv[N_CAP];                        // deg -> rsqrt(deg)
__device__ float g_h1[(size_t)N_CAP * H_CAP];          // X @ W1
__device__ float g_o1[(size_t)N_CAP * H_CAP];          // aggregated layer-1 (then relu'd in place)
__device__ float g_h2[(size_t)N_CAP * C_CAP];          // x1 @ W2
__device__ int   g_is64;                               // edge_index dtype flag

// ---------------------------------------------------------------------------
// edge_index accessor: layout is [2, E]; row = ei[e], col = ei[E + e].
// ---------------------------------------------------------------------------
__device__ __forceinline__ void edge_rc(const void* ei, int is64, long long E,
                                        long long e, int& r, int& c) {
    if (is64) {
        const long long* p = (const long long*)ei;
        r = (int)p[e];
        c = (int)p[E + e];
    } else {
        const int* p = (const int*)ei;
        r = p[e];
        c = p[E + e];
    }
}

// ---------------------------------------------------------------------------
// Detect int64 vs int32 edge_index: viewed as u32, int64 node ids (<50000,
// nonnegative) have every odd word == 0. 2*E u32 words are safe to read
// under both interpretations.
// ---------------------------------------------------------------------------
__global__ void k_detect(const unsigned int* p, long long n32) {
    __shared__ unsigned int s;
    if (threadIdx.x == 0) s = 0u;
    __syncthreads();
    unsigned int v = 0u;
    long long lim = n32 < 16384 ? n32 : 16384;
    for (long long i = 1 + 2 * (long long)threadIdx.x; i < lim; i += 2 * (long long)blockDim.x)
        v |= p[i];
    atomicOr(&s, v);
    __syncthreads();
    if (threadIdx.x == 0) g_is64 = (s == 0u) ? 1 : 0;
}

// ---------------------------------------------------------------------------
// Degree: deg[i] = 1 (self loop) + sum_{e: col==i} w[e];  then dinv = rsqrt.
// ---------------------------------------------------------------------------
__global__ void k_deg_init(int N) {
    int i = blockIdx.x * blockDim.x + threadIdx.x;
    if (i < N) g_dinv[i] = 1.0f;
}

__global__ void k_deg_acc(const void* ei, const float* __restrict__ w, int E) {
    int e = blockIdx.x * blockDim.x + threadIdx.x;
    if (e < E) {
        int is64 = g_is64;
        int r, c;
        edge_rc(ei, is64, E, e, r, c);
        atomicAdd(&g_dinv[c], w[e]);
    }
}

__global__ void k_rsqrt(int N) {
    int i = blockIdx.x * blockDim.x + threadIdx.x;
    if (i < N) g_dinv[i] = rsqrtf(g_dinv[i]);   // deg >= 1 always
}

// ---------------------------------------------------------------------------
// GEMM1: g_h1[M,128] = A[M,K] @ B[K,128].  BM=128, BN=128, BK=8, 256 thr,
// 8x8 microtile per thread. Assumes H == 128, K % 8 == 0.
// ---------------------------------------------------------------------------
__global__ __launch_bounds__(256) void k_gemm1(const float* __restrict__ A,
                                               const float* __restrict__ B,
                                               int M, int K) {
    __shared__ float As[8][128];
    __shared__ float Bs[8][128];
    int tid = threadIdx.x;
    int m0 = blockIdx.x * 128;
    int tx = tid & 15, ty = tid >> 4;

    float acc[8][8];
#pragma unroll
    for (int i = 0; i < 8; i++)
#pragma unroll
        for (int j = 0; j < 8; j++) acc[i][j] = 0.0f;

    int arow = tid >> 1, acg = (tid & 1) * 4;   // A: 128 rows x 8 cols
    int brow = tid >> 5, bc = (tid & 31) * 4;   // B: 8 rows x 128 cols

    for (int k0 = 0; k0 < K; k0 += 8) {
        float4 av = make_float4(0.f, 0.f, 0.f, 0.f);
        int gr = m0 + arow;
        if (gr < M) av = *(const float4*)(A + (size_t)gr * K + k0 + acg);
        As[acg + 0][arow] = av.x;
        As[acg + 1][arow] = av.y;
        As[acg + 2][arow] = av.z;
        As[acg + 3][arow] = av.w;
        *(float4*)&Bs[brow][bc] = *(const float4*)(B + (size_t)(k0 + brow) * 128 + bc);
        __syncthreads();

#pragma unroll
        for (int kk = 0; kk < 8; kk++) {
            float a[8], b[8];
            *(float4*)&a[0] = *(const float4*)&As[kk][ty * 8];
            *(float4*)&a[4] = *(const float4*)&As[kk][ty * 8 + 4];
            *(float4*)&b[0] = *(const float4*)&Bs[kk][tx * 8];
            *(float4*)&b[4] = *(const float4*)&Bs[kk][tx * 8 + 4];
#pragma unroll
            for (int i = 0; i < 8; i++)
#pragma unroll
                for (int j = 0; j < 8; j++) acc[i][j] += a[i] * b[j];
        }
        __syncthreads();
    }

#pragma unroll
    for (int i = 0; i < 8; i++) {
        int gr = m0 + ty * 8 + i;
        if (gr < M) {
            float* cp = g_h1 + (size_t)gr * 128 + tx * 8;
            *(float4*)cp       = make_float4(acc[i][0], acc[i][1], acc[i][2], acc[i][3]);
            *(float4*)(cp + 4) = make_float4(acc[i][4], acc[i][5], acc[i][6], acc[i][7]);
        }
    }
}

// ---------------------------------------------------------------------------
// Layer-1 aggregation: self-loop init, edge scatter (atomics), bias+relu.
// ---------------------------------------------------------------------------
__global__ void k_self1(int N) {
    size_t idx = (size_t)blockIdx.x * blockDim.x + threadIdx.x;
    if (idx < (size_t)N * 128) {
        int i = (int)(idx >> 7);
        float d = g_dinv[i];
        g_o1[idx] = d * d * g_h1[idx];
    }
}

__global__ void k_agg1(const void* ei, const float* __restrict__ w, int E) {
    int warp = (blockIdx.x * blockDim.x + threadIdx.x) >> 5;
    int lane = threadIdx.x & 31;
    if (warp < E) {
        int is64 = g_is64;
        int r, c;
        edge_rc(ei, is64, E, warp, r, c);
        float nr = g_dinv[r] * w[warp] * g_dinv[c];
        float4 v = *(const float4*)(g_h1 + (size_t)r * 128 + lane * 4);
        float* op = g_o1 + (size_t)c * 128 + lane * 4;
        atomicAdd(op + 0, v.x * nr);
        atomicAdd(op + 1, v.y * nr);
        atomicAdd(op + 2, v.z * nr);
        atomicAdd(op + 3, v.w * nr);
    }
}

__global__ void k_bias_relu1(const float* __restrict__ b1, int N) {
    size_t idx = (size_t)blockIdx.x * blockDim.x + threadIdx.x;
    if (idx < (size_t)N * 128) {
        int f = (int)(idx & 127);
        g_o1[idx] = fmaxf(g_o1[idx] + b1[f], 0.0f);
    }
}

// ---------------------------------------------------------------------------
// GEMM2: g_h2[N,C] = x1[N,128] @ W2[128,C].  One warp per node, W2 in smem.
// ---------------------------------------------------------------------------
__global__ __launch_bounds__(128) void k_gemm2(const float* __restrict__ W2, int N, int C) {
    __shared__ float Ws[128 * C_CAP];
    for (int i = threadIdx.x; i < 128 * C; i += blockDim.x) Ws[i] = W2[i];
    __syncthreads();
    int warp = threadIdx.x >> 5;
    int lane = threadIdx.x & 31;
    int n = blockIdx.x * 4 + warp;
    if (n >= N) return;
    const float* xr = g_o1 + (size_t)n * 128;
    float a0 = 0.f, a1 = 0.f;
    int c1 = lane + 32;
#pragma unroll 4
    for (int k = 0; k < 128; k++) {
        float xv = xr[k];
        a0 += xv * Ws[k * C + lane];
        a1 += xv * Ws[k * C + (c1 < C ? c1 : 0)];
    }
    g_h2[(size_t)n * C + lane] = a0;
    if (c1 < C) g_h2[(size_t)n * C + c1] = a1;
}

// ---------------------------------------------------------------------------
// Layer-2 aggregation into d_out: self-loop + bias init, edge scatter.
// ---------------------------------------------------------------------------
__global__ void k_self2(float* __restrict__ out, const float* __restrict__ b2, int N, int C) {
    long long idx = (long long)blockIdx.x * blockDim.x + threadIdx.x;
    if (idx < (long long)N * C) {
        int i = (int)(idx / C);
        int c = (int)(idx % C);
        float d = g_dinv[i];
        out[idx] = d * d * g_h2[idx] + b2[c];
    }
}

__global__ void k_agg2(const void* ei, const float* __restrict__ w,
                       float* __restrict__ out, int E, int C) {
    int warp = (blockIdx.x * blockDim.x + threadIdx.x) >> 5;
    int lane = threadIdx.x & 31;
    if (warp < E) {
        int is64 = g_is64;
        int r, c;
        edge_rc(ei, is64, E, warp, r, c);
        float nr = g_dinv[r] * w[warp] * g_dinv[c];
        const float* hp = g_h2 + (size_t)r * C;
        float* op = out + (size_t)c * C;
        for (int f = lane; f < C; f += 32) atomicAdd(op + f, nr * hp[f]);
    }
}

// ---------------------------------------------------------------------------
// log_softmax over C classes, one warp per node, in place on d_out.
// ---------------------------------------------------------------------------
__global__ void k_logsoftmax(float* __restrict__ out, int N, int C) {
    int warp = (blockIdx.x * blockDim.x + threadIdx.x) >> 5;
    int lane = threadIdx.x & 31;
    if (warp >= N) return;
    float* z = out + (size_t)warp * C;
    const float NEG_INF = __int_as_float(0xff800000);
    float v0 = (lane < C) ? z[lane] : NEG_INF;
    float v1 = (lane + 32 < C) ? z[lane + 32] : NEG_INF;
    float m = fmaxf(v0, v1);
#pragma unroll
    for (int o = 16; o > 0; o >>= 1) m = fmaxf(m, __shfl_xor_sync(0xffffffffu, m, o));
    float s = ((lane < C) ? expf(v0 - m) : 0.f) + ((lane + 32 < C) ? expf(v1 - m) : 0.f);
#pragma unroll
    for (int o = 16; o > 0; o >>= 1) s += __shfl_xor_sync(0xffffffffu, s, o);
    float l = logf(s);
    if (lane < C) z[lane] = v0 - m - l;
    if (lane + 32 < C) z[lane + 32] = v1 - m - l;
}

// ---------------------------------------------------------------------------
extern "C" void kernel_launch(void* const* d_in, const int* in_sizes, int n_in,
                              void* d_out, int out_size) {
    const float* feat = (const float*)d_in[0];
    const void*  ei   = d_in[1];
    const float* ew   = (const float*)d_in[2];
    const float* W1   = (const float*)d_in[3];
    const float* b1   = (const float*)d_in[4];
    const float* W2   = (const float*)d_in[5];
    const float* b2   = (const float*)d_in[6];
    float* out = (float*)d_out;

    int H   = in_sizes[4];                 // 128
    int FIN = in_sizes[3] / H;             // 512
    int N   = in_sizes[0] / FIN;           // 50000
    int C   = in_sizes[6];                 // 40
    int E   = in_sizes[2];                 // 800000
    (void)n_in; (void)out_size; (void)H;

    k_detect<<<1, 256>>>((const unsigned int*)ei, (long long)2 * E);
    k_deg_init<<<(N + 255) / 256, 256>>>(N);
    k_deg_acc<<<(E + 255) / 256, 256>>>(ei, ew, E);
    k_rsqrt<<<(N + 255) / 256, 256>>>(N);

    k_gemm1<<<(N + 127) / 128, 256>>>(feat, W1, N, FIN);

    long long n1 = (long long)N * 128;
    k_self1<<<(int)((n1 + 255) / 256), 256>>>(N);
    k_agg1<<<(E + 7) / 8, 256>>>(ei, ew, E);
    k_bias_relu1<<<(int)((n1 + 255) / 256), 256>>>(b1, N);

    k_gemm2<<<(N + 3) / 4, 128>>>(W2, N, C);

    long long n2 = (long long)N * C;
    k_self2<<<(int)((n2 + 255) / 256), 256>>>(out, b2, N, C);
    k_agg2<<<(E + 7) / 8, 256>>>(ei, ew, out, E, C);

    k_logsoftmax<<<(N + 7) / 8, 256>>>(out, N, C);
}

// round 3
// speedup vs baseline: 1.5156x; 1.5156x over previous
#include <cuda_runtime.h>
#include <cuda_bf16.h>
#include <stdint.h>

#define N_CAP 50000
#define H_CAP 128
#define C_CAP 64
#define KMAX  512

__device__ float g_dinv[N_CAP];
__device__ float g_h1[(size_t)N_CAP * H_CAP];
__device__ float g_o1[(size_t)N_CAP * H_CAP];
__device__ float g_h2[(size_t)N_CAP * C_CAP];
__device__ int   g_is64;
// W1 transposed + split: [n(0..127)][k(0..511)] bf16 hi/lo.
__device__ __nv_bfloat16 g_Bhi[H_CAP * KMAX];
__device__ __nv_bfloat16 g_Blo[H_CAP * KMAX];

// ---------------------------------------------------------------------------
// edge_index accessor + dtype detect
// ---------------------------------------------------------------------------
__device__ __forceinline__ void edge_rc(const void* ei, int is64, long long E,
                                        long long e, int& r, int& c) {
    if (is64) {
        const long long* p = (const long long*)ei;
        r = (int)p[e]; c = (int)p[E + e];
    } else {
        const int* p = (const int*)ei;
        r = p[e]; c = p[E + e];
    }
}

__global__ void k_detect(const unsigned int* p, long long n32) {
    __shared__ unsigned int s;
    if (threadIdx.x == 0) s = 0u;
    __syncthreads();
    unsigned int v = 0u;
    long long lim = n32 < 16384 ? n32 : 16384;
    for (long long i = 1 + 2 * (long long)threadIdx.x; i < lim; i += 2 * (long long)blockDim.x)
        v |= p[i];
    atomicOr(&s, v);
    __syncthreads();
    if (threadIdx.x == 0) g_is64 = (s == 0u) ? 1 : 0;
}

// ---------------------------------------------------------------------------
// degree / dinv
// ---------------------------------------------------------------------------
__global__ void k_deg_init(int N) {
    int i = blockIdx.x * blockDim.x + threadIdx.x;
    if (i < N) g_dinv[i] = 1.0f;
}
__global__ void k_deg_acc(const void* ei, const float* __restrict__ w, int E) {
    int e = blockIdx.x * blockDim.x + threadIdx.x;
    if (e < E) {
        int r, c;
        edge_rc(ei, g_is64, E, e, r, c);
        atomicAdd(&g_dinv[c], w[e]);
    }
}
__global__ void k_rsqrt(int N) {
    int i = blockIdx.x * blockDim.x + threadIdx.x;
    if (i < N) g_dinv[i] = rsqrtf(g_dinv[i]);
}

// ---------------------------------------------------------------------------
// Pre-split + transpose W1 ([K][128] -> [n][K] hi/lo bf16)
// ---------------------------------------------------------------------------
__global__ void k_prepB(const float* __restrict__ W1, int K) {
    int idx = blockIdx.x * blockDim.x + threadIdx.x;
    if (idx >= K * 128) return;
    int k = idx >> 7, n = idx & 127;
    float x = W1[(size_t)k * 128 + n];
    __nv_bfloat16 h = __float2bfloat16(x);
    __nv_bfloat16 l = __float2bfloat16(x - __bfloat162float(h));
    g_Bhi[(size_t)n * K + k] = h;
    g_Blo[(size_t)n * K + k] = l;
}

// ---------------------------------------------------------------------------
// GEMM1: g_h1[M,128] = A[M,K] @ W1[K,128] via mma.sync bf16 split.
// Block tile 128x128, K-tile 32. 8 warps (4 along M x 2 along N),
// warp tile 32(M) x 64(N). Padded smem rows: 32 bf16 + 8 pad = stride 40.
// ---------------------------------------------------------------------------
#define AST 40   // smem row stride in bf16

__device__ __forceinline__ void mma_bf16(float* c, const uint32_t* a, const uint32_t* b) {
    asm volatile(
        "mma.sync.aligned.m16n8k16.row.col.f32.bf16.bf16.f32 "
        "{%0,%1,%2,%3}, {%4,%5,%6,%7}, {%8,%9}, {%0,%1,%2,%3};"
        : "+f"(c[0]), "+f"(c[1]), "+f"(c[2]), "+f"(c[3])
        : "r"(a[0]), "r"(a[1]), "r"(a[2]), "r"(a[3]), "r"(b[0]), "r"(b[1]));
}
__device__ __forceinline__ void ldsm4(uint32_t* r, uint32_t addr) {
    asm volatile("ldmatrix.sync.aligned.m8n8.x4.shared.b16 {%0,%1,%2,%3}, [%4];"
                 : "=r"(r[0]), "=r"(r[1]), "=r"(r[2]), "=r"(r[3]) : "r"(addr));
}

__global__ __launch_bounds__(256, 1) void k_gemm1_mma(const float* __restrict__ A,
                                                      int M, int K) {
    __shared__ __nv_bfloat16 sAhi[128 * AST];
    __shared__ __nv_bfloat16 sAlo[128 * AST];
    __shared__ __nv_bfloat16 sBhi[128 * AST];
    __shared__ __nv_bfloat16 sBlo[128 * AST];

    int tid = threadIdx.x, wid = tid >> 5, lane = tid & 31;
    int m0 = blockIdx.x * 128;
    int wm = (wid & 3) * 32;        // warp M offset (0..96)
    int wn = (wid >> 2) * 64;       // warp N offset (0 or 64)

    uint32_t uAhi = (uint32_t)__cvta_generic_to_shared(sAhi);
    uint32_t uAlo = (uint32_t)__cvta_generic_to_shared(sAlo);
    uint32_t uBhi = (uint32_t)__cvta_generic_to_shared(sBhi);
    uint32_t uBlo = (uint32_t)__cvta_generic_to_shared(sBlo);

    float acc[2][8][4];
#pragma unroll
    for (int i = 0; i < 2; i++)
#pragma unroll
        for (int j = 0; j < 8; j++)
#pragma unroll
            for (int q = 0; q < 4; q++) acc[i][j][q] = 0.0f;

    // ldmatrix per-lane address components
    int a_row = (lane & 7) + ((lane >> 3) & 1) * 8;   // within 16-row frag
    int a_kof = (lane >> 4) * 8;
    int b_row = (lane & 7) + ((lane >> 4) ? 8 : 0);   // within 16-n frag
    int b_kof = ((lane >> 3) & 1) * 8;

    int ktiles = K >> 5;
    for (int kt = 0; kt < ktiles; kt++) {
        int k0 = kt << 5;

        // stage A: 128x32 fp32 -> regs
        float4 av[4];
#pragma unroll
        for (int it = 0; it < 4; it++) {
            int slot = tid + it * 256;            // 0..1023
            int r = slot >> 3, c4 = (slot & 7) << 2;
            int gr = m0 + r;
            av[it] = make_float4(0.f, 0.f, 0.f, 0.f);
            if (gr < M) av[it] = *(const float4*)(A + (size_t)gr * K + k0 + c4);
        }
        // stage B: 128 rows x 64B hi/lo -> regs
        uint4 bh[2], bl[2];
#pragma unroll
        for (int it = 0; it < 2; it++) {
            int slot = tid + it * 256;            // 0..511
            int n = slot >> 2, q = slot & 3;
            bh[it] = *(const uint4*)(g_Bhi + (size_t)n * K + k0 + q * 8);
            bl[it] = *(const uint4*)(g_Blo + (size_t)n * K + k0 + q * 8);
        }

        __syncthreads();   // previous tile fully consumed

#pragma unroll
        for (int it = 0; it < 4; it++) {
            int slot = tid + it * 256;
            int r = slot >> 3, c4 = (slot & 7) << 2;
            float4 v = av[it];
            __nv_bfloat16 hx = __float2bfloat16(v.x), hy = __float2bfloat16(v.y);
            __nv_bfloat16 hz = __float2bfloat16(v.z), hw = __float2bfloat16(v.w);
            __nv_bfloat162 h01(hx, hy), h23(hz, hw);
            __nv_bfloat162 l01(__float2bfloat16(v.x - __bfloat162float(hx)),
                               __float2bfloat16(v.y - __bfloat162float(hy)));
            __nv_bfloat162 l23(__float2bfloat16(v.z - __bfloat162float(hz)),
                               __float2bfloat16(v.w - __bfloat162float(hw)));
            *(uint2*)&sAhi[r * AST + c4] = make_uint2(*(uint32_t*)&h01, *(uint32_t*)&h23);
            *(uint2*)&sAlo[r * AST + c4] = make_uint2(*(uint32_t*)&l01, *(uint32_t*)&l23);
        }
#pragma unroll
        for (int it = 0; it < 2; it++) {
            int slot = tid + it * 256;
            int n = slot >> 2, q = slot & 3;
            *(uint4*)&sBhi[n * AST + q * 8] = bh[it];
            *(uint4*)&sBlo[n * AST + q * 8] = bl[it];
        }
        __syncthreads();

#pragma unroll
        for (int ks = 0; ks < 32; ks += 16) {
            uint32_t ahi[2][4], alo[2][4];
#pragma unroll
            for (int mf = 0; mf < 2; mf++) {
                uint32_t off = ((wm + mf * 16 + a_row) * AST + ks + a_kof) * 2;
                ldsm4(ahi[mf], uAhi + off);
                ldsm4(alo[mf], uAlo + off);
            }
#pragma unroll
            for (int np = 0; np < 4; np++) {
                uint32_t off = ((wn + np * 16 + b_row) * AST + ks + b_kof) * 2;
                uint32_t bhf[4], blf[4];
                ldsm4(bhf, uBhi + off);
                ldsm4(blf, uBlo + off);
#pragma unroll
                for (int mf = 0; mf < 2; mf++) {
                    mma_bf16(acc[mf][np * 2], ahi[mf], bhf);
                    mma_bf16(acc[mf][np * 2], ahi[mf], blf);
                    mma_bf16(acc[mf][np * 2], alo[mf], bhf);
                    mma_bf16(acc[mf][np * 2 + 1], ahi[mf], bhf + 2);
                    mma_bf16(acc[mf][np * 2 + 1], ahi[mf], blf + 2);
                    mma_bf16(acc[mf][np * 2 + 1], alo[mf], bhf + 2);
                }
            }
        }
    }

    // epilogue: scatter accumulators to g_h1
    int qr = lane >> 2, qc = (lane & 3) * 2;
#pragma unroll
    for (int mf = 0; mf < 2; mf++) {
        int r0 = m0 + wm + mf * 16 + qr;
#pragma unroll
        for (int nf = 0; nf < 8; nf++) {
            int cc = wn + nf * 8 + qc;
            if (r0 < M)
                *(float2*)(g_h1 + (size_t)r0 * 128 + cc) =
                    make_float2(acc[mf][nf][0], acc[mf][nf][1]);
            if (r0 + 8 < M)
                *(float2*)(g_h1 + (size_t)(r0 + 8) * 128 + cc) =
                    make_float2(acc[mf][nf][2], acc[mf][nf][3]);
        }
    }
}

// ---------------------------------------------------------------------------
// Layer-1 aggregation
// ---------------------------------------------------------------------------
__global__ void k_self1(int N) {
    size_t idx = (size_t)blockIdx.x * blockDim.x + threadIdx.x;
    if (idx < (size_t)N * 128) {
        int i = (int)(idx >> 7);
        float d = g_dinv[i];
        g_o1[idx] = d * d * g_h1[idx];
    }
}

__global__ void k_agg1(const void* ei, const float* __restrict__ w, int E) {
    int warp = (blockIdx.x * blockDim.x + threadIdx.x) >> 5;
    int lane = threadIdx.x & 31;
    if (warp < E) {
        int r, c;
        edge_rc(ei, g_is64, E, warp, r, c);
        float nr = g_dinv[r] * w[warp] * g_dinv[c];
        float4 v = *(const float4*)(g_h1 + (size_t)r * 128 + lane * 4);
        float* op = g_o1 + (size_t)c * 128 + lane * 4;
        asm volatile("red.global.add.v4.f32 [%0], {%1, %2, %3, %4};"
                     :: "l"(op), "f"(v.x * nr), "f"(v.y * nr), "f"(v.z * nr), "f"(v.w * nr)
                     : "memory");
    }
}

__global__ void k_bias_relu1(const float* __restrict__ b1, int N) {
    size_t idx = (size_t)blockIdx.x * blockDim.x + threadIdx.x;
    if (idx < (size_t)N * 128) {
        int f = (int)(idx & 127);
        g_o1[idx] = fmaxf(g_o1[idx] + b1[f], 0.0f);
    }
}

// ---------------------------------------------------------------------------
// GEMM2: h2[N,C] = o1[N,128] @ W2[128,C]
// ---------------------------------------------------------------------------
__global__ __launch_bounds__(128) void k_gemm2(const float* __restrict__ W2, int N, int C) {
    __shared__ float Ws[128 * C_CAP];
    for (int i = threadIdx.x; i < 128 * C; i += blockDim.x) Ws[i] = W2[i];
    __syncthreads();
    int warp = threadIdx.x >> 5;
    int lane = threadIdx.x & 31;
    int n = blockIdx.x * 4 + warp;
    if (n >= N) return;
    const float* xr = g_o1 + (size_t)n * 128;
    float a0 = 0.f, a1 = 0.f;
    int c1 = lane + 32;
#pragma unroll 4
    for (int k = 0; k < 128; k++) {
        float xv = xr[k];
        a0 += xv * Ws[k * C + lane];
        a1 += xv * Ws[k * C + (c1 < C ? c1 : 0)];
    }
    g_h2[(size_t)n * C + lane] = a0;
    if (c1 < C) g_h2[(size_t)n * C + c1] = a1;
}

// ---------------------------------------------------------------------------
// Layer-2 aggregation into d_out
// ---------------------------------------------------------------------------
__global__ void k_self2(float* __restrict__ out, const float* __restrict__ b2, int N, int C) {
    long long idx = (long long)blockIdx.x * blockDim.x + threadIdx.x;
    if (idx < (long long)N * C) {
        int i = (int)(idx / C);
        int c = (int)(idx % C);
        float d = g_dinv[i];
        out[idx] = d * d * g_h2[idx] + b2[c];
    }
}

__global__ void k_agg2(const void* ei, const float* __restrict__ w,
                       float* __restrict__ out, int E, int C) {
    int warp = (blockIdx.x * blockDim.x + threadIdx.x) >> 5;
    int lane = threadIdx.x & 31;
    if (warp < E) {
        int r, c;
        edge_rc(ei, g_is64, E, warp, r, c);
        float nr = g_dinv[r] * w[warp] * g_dinv[c];
        const float* hp = g_h2 + (size_t)r * C;
        float* op = out + (size_t)c * C;
        int C4 = C & ~3;
        for (int f = lane * 4; f < C4; f += 128) {
            float4 v = *(const float4*)(hp + f);
            asm volatile("red.global.add.v4.f32 [%0], {%1, %2, %3, %4};"
                         :: "l"(op + f), "f"(v.x * nr), "f"(v.y * nr), "f"(v.z * nr), "f"(v.w * nr)
                         : "memory");
        }
        for (int f = C4 + lane; f < C; f += 32) atomicAdd(op + f, nr * hp[f]);
    }
}

// ---------------------------------------------------------------------------
// log_softmax
// ---------------------------------------------------------------------------
__global__ void k_logsoftmax(float* __restrict__ out, int N, int C) {
    int warp = (blockIdx.x * blockDim.x + threadIdx.x) >> 5;
    int lane = threadIdx.x & 31;
    if (warp >= N) return;
    float* z = out + (size_t)warp * C;
    const float NEG_INF = __int_as_float(0xff800000);
    float v0 = (lane < C) ? z[lane] : NEG_INF;
    float v1 = (lane + 32 < C) ? z[lane + 32] : NEG_INF;
    float m = fmaxf(v0, v1);
#pragma unroll
    for (int o = 16; o > 0; o >>= 1) m = fmaxf(m, __shfl_xor_sync(0xffffffffu, m, o));
    float s = ((lane < C) ? expf(v0 - m) : 0.f) + ((lane + 32 < C) ? expf(v1 - m) : 0.f);
#pragma unroll
    for (int o = 16; o > 0; o >>= 1) s += __shfl_xor_sync(0xffffffffu, s, o);
    float l = logf(s);
    if (lane < C) z[lane] = v0 - m - l;
    if (lane + 32 < C) z[lane + 32] = v1 - m - l;
}

// ---------------------------------------------------------------------------
extern "C" void kernel_launch(void* const* d_in, const int* in_sizes, int n_in,
                              void* d_out, int out_size) {
    const float* feat = (const float*)d_in[0];
    const void*  ei   = d_in[1];
    const float* ew   = (const float*)d_in[2];
    const float* W1   = (const float*)d_in[3];
    const float* b1   = (const float*)d_in[4];
    const float* W2   = (const float*)d_in[5];
    const float* b2   = (const float*)d_in[6];
    float* out = (float*)d_out;

    int H   = in_sizes[4];                 // 128
    int FIN = in_sizes[3] / H;             // 512
    int N   = in_sizes[0] / FIN;           // 50000
    int C   = in_sizes[6];                 // 40
    int E   = in_sizes[2];                 // 800000
    (void)n_in; (void)out_size;

    k_detect<<<1, 256>>>((const unsigned int*)ei, (long long)2 * E);
    k_deg_init<<<(N + 255) / 256, 256>>>(N);
    k_deg_acc<<<(E + 255) / 256, 256>>>(ei, ew, E);
    k_rsqrt<<<(N + 255) / 256, 256>>>(N);

    k_prepB<<<(FIN * 128 + 255) / 256, 256>>>(W1, FIN);
    k_gemm1_mma<<<(N + 127) / 128, 256>>>(feat, N, FIN);

    long long n1 = (long long)N * 128;
    k_self1<<<(int)((n1 + 255) / 256), 256>>>(N);
    k_agg1<<<(E + 7) / 8, 256>>>(ei, ew, E);
    k_bias_relu1<<<(int)((n1 + 255) / 256), 256>>>(b1, N);

    k_gemm2<<<(N + 3) / 4, 128>>>(W2, N, C);

    long long n2 = (long long)N * C;
    k_self2<<<(int)((n2 + 255) / 256), 256>>>(out, b2, N, C);
    k_agg2<<<(E + 7) / 8, 256>>>(ei, ew, out, E, C);

    k_logsoftmax<<<(N + 7) / 8, 256>>>(out, N, C);
}

// round 4
// speedup vs baseline: 1.8316x; 1.2085x over previous
#include <cuda_runtime.h>
#include <cuda_bf16.h>
#include <stdint.h>

#define N_CAP 50000
#define E_CAP 1000000
#define H_CAP 128
#define C_CAP 64
#define KMAX  512

__device__ float g_dinv[N_CAP];
__device__ int   g_cnt[N_CAP];       // in-degree (edges only)
__device__ int   g_rs[N_CAP];        // CSR row start (by destination)
__device__ int   g_cur[N_CAP];       // fill cursor
__device__ uint2 g_epay[E_CAP];      // {src row, norm} per edge, CSR order
__device__ float g_h1[(size_t)N_CAP * H_CAP];
__device__ float g_o1[(size_t)N_CAP * H_CAP];
__device__ float g_h2[(size_t)N_CAP * C_CAP];
__device__ int   g_is64;
__device__ __nv_bfloat16 g_Bhi[H_CAP * KMAX];
__device__ __nv_bfloat16 g_Blo[H_CAP * KMAX];

// ---------------------------------------------------------------------------
__device__ __forceinline__ void edge_rc(const void* ei, int is64, long long E,
                                        long long e, int& r, int& c) {
    if (is64) {
        const long long* p = (const long long*)ei;
        r = (int)p[e]; c = (int)p[E + e];
    } else {
        const int* p = (const int*)ei;
        r = p[e]; c = p[E + e];
    }
}

__global__ void k_detect(const unsigned int* p, long long n32) {
    __shared__ unsigned int s;
    if (threadIdx.x == 0) s = 0u;
    __syncthreads();
    unsigned int v = 0u;
    long long lim = n32 < 16384 ? n32 : 16384;
    for (long long i = 1 + 2 * (long long)threadIdx.x; i < lim; i += 2 * (long long)blockDim.x)
        v |= p[i];
    atomicOr(&s, v);
    __syncthreads();
    if (threadIdx.x == 0) g_is64 = (s == 0u) ? 1 : 0;
}

// ---------------------------------------------------------------------------
// degree + edge-count in one pass
// ---------------------------------------------------------------------------
__global__ void k_deg_init(int N) {
    int i = blockIdx.x * blockDim.x + threadIdx.x;
    if (i < N) { g_dinv[i] = 1.0f; g_cnt[i] = 0; }
}
__global__ void k_deg_count(const void* ei, const float* __restrict__ w, int E) {
    int e = blockIdx.x * blockDim.x + threadIdx.x;
    if (e < E) {
        int r, c;
        edge_rc(ei, g_is64, E, e, r, c);
        atomicAdd(&g_dinv[c], w[e]);
        atomicAdd(&g_cnt[c], 1);
    }
}
__global__ void k_rsqrt(int N) {
    int i = blockIdx.x * blockDim.x + threadIdx.x;
    if (i < N) g_dinv[i] = rsqrtf(g_dinv[i]);
}

// ---------------------------------------------------------------------------
// exclusive scan of g_cnt -> g_rs, g_cur.  Single block, 1024 threads.
// ---------------------------------------------------------------------------
__global__ __launch_bounds__(1024) void k_scan(int N) {
    __shared__ int sh[1024];
    __shared__ int run;
    int tid = threadIdx.x;
    if (tid == 0) run = 0;
    __syncthreads();
    for (int base = 0; base < N; base += 1024) {
        int idx = base + tid;
        int v = (idx < N) ? g_cnt[idx] : 0;
        sh[tid] = v;
        __syncthreads();
        for (int off = 1; off < 1024; off <<= 1) {
            int t = (tid >= off) ? sh[tid - off] : 0;
            __syncthreads();
            sh[tid] += t;
            __syncthreads();
        }
        int excl = sh[tid] - v + run;
        if (idx < N) { g_rs[idx] = excl; g_cur[idx] = excl; }
        int total = sh[1023];
        __syncthreads();
        if (tid == 0) run += total;
        __syncthreads();
    }
}

// ---------------------------------------------------------------------------
// CSR fill: payload = {src row, dinv[r]*w*dinv[c]}
// ---------------------------------------------------------------------------
__global__ void k_fill(const void* ei, const float* __restrict__ w, int E) {
    int e = blockIdx.x * blockDim.x + threadIdx.x;
    if (e < E) {
        int r, c;
        edge_rc(ei, g_is64, E, e, r, c);
        float nr = g_dinv[r] * w[e] * g_dinv[c];
        int pos = atomicAdd(&g_cur[c], 1);
        g_epay[pos] = make_uint2((unsigned)r, __float_as_uint(nr));
    }
}

// ---------------------------------------------------------------------------
// W1 pre-split + transpose
// ---------------------------------------------------------------------------
__global__ void k_prepB(const float* __restrict__ W1, int K) {
    int idx = blockIdx.x * blockDim.x + threadIdx.x;
    if (idx >= K * 128) return;
    int k = idx >> 7, n = idx & 127;
    float x = W1[(size_t)k * 128 + n];
    __nv_bfloat16 h = __float2bfloat16(x);
    __nv_bfloat16 l = __float2bfloat16(x - __bfloat162float(h));
    g_Bhi[(size_t)n * K + k] = h;
    g_Blo[(size_t)n * K + k] = l;
}

// ---------------------------------------------------------------------------
// GEMM1 (unchanged from R3): 128x128 block, bf16-split mma.sync
// ---------------------------------------------------------------------------
#define AST 40

__device__ __forceinline__ void mma_bf16(float* c, const uint32_t* a, const uint32_t* b) {
    asm volatile(
        "mma.sync.aligned.m16n8k16.row.col.f32.bf16.bf16.f32 "
        "{%0,%1,%2,%3}, {%4,%5,%6,%7}, {%8,%9}, {%0,%1,%2,%3};"
        : "+f"(c[0]), "+f"(c[1]), "+f"(c[2]), "+f"(c[3])
        : "r"(a[0]), "r"(a[1]), "r"(a[2]), "r"(a[3]), "r"(b[0]), "r"(b[1]));
}
__device__ __forceinline__ void ldsm4(uint32_t* r, uint32_t addr) {
    asm volatile("ldmatrix.sync.aligned.m8n8.x4.shared.b16 {%0,%1,%2,%3}, [%4];"
                 : "=r"(r[0]), "=r"(r[1]), "=r"(r[2]), "=r"(r[3]) : "r"(addr));
}

__global__ __launch_bounds__(256, 1) void k_gemm1_mma(const float* __restrict__ A,
                                                      int M, int K) {
    __shared__ __nv_bfloat16 sAhi[128 * AST];
    __shared__ __nv_bfloat16 sAlo[128 * AST];
    __shared__ __nv_bfloat16 sBhi[128 * AST];
    __shared__ __nv_bfloat16 sBlo[128 * AST];

    int tid = threadIdx.x, wid = tid >> 5, lane = tid & 31;
    int m0 = blockIdx.x * 128;
    int wm = (wid & 3) * 32;
    int wn = (wid >> 2) * 64;

    uint32_t uAhi = (uint32_t)__cvta_generic_to_shared(sAhi);
    uint32_t uAlo = (uint32_t)__cvta_generic_to_shared(sAlo);
    uint32_t uBhi = (uint32_t)__cvta_generic_to_shared(sBhi);
    uint32_t uBlo = (uint32_t)__cvta_generic_to_shared(sBlo);

    float acc[2][8][4];
#pragma unroll
    for (int i = 0; i < 2; i++)
#pragma unroll
        for (int j = 0; j < 8; j++)
#pragma unroll
            for (int q = 0; q < 4; q++) acc[i][j][q] = 0.0f;

    int a_row = (lane & 7) + ((lane >> 3) & 1) * 8;
    int a_kof = (lane >> 4) * 8;
    int b_row = (lane & 7) + ((lane >> 4) ? 8 : 0);
    int b_kof = ((lane >> 3) & 1) * 8;

    int ktiles = K >> 5;
    for (int kt = 0; kt < ktiles; kt++) {
        int k0 = kt << 5;
        float4 av[4];
#pragma unroll
        for (int it = 0; it < 4; it++) {
            int slot = tid + it * 256;
            int r = slot >> 3, c4 = (slot & 7) << 2;
            int gr = m0 + r;
            av[it] = make_float4(0.f, 0.f, 0.f, 0.f);
            if (gr < M) av[it] = *(const float4*)(A + (size_t)gr * K + k0 + c4);
        }
        uint4 bh[2], bl[2];
#pragma unroll
        for (int it = 0; it < 2; it++) {
            int slot = tid + it * 256;
            int n = slot >> 2, q = slot & 3;
            bh[it] = *(const uint4*)(g_Bhi + (size_t)n * K + k0 + q * 8);
            bl[it] = *(const uint4*)(g_Blo + (size_t)n * K + k0 + q * 8);
        }
        __syncthreads();
#pragma unroll
        for (int it = 0; it < 4; it++) {
            int slot = tid + it * 256;
            int r = slot >> 3, c4 = (slot & 7) << 2;
            float4 v = av[it];
            __nv_bfloat16 hx = __float2bfloat16(v.x), hy = __float2bfloat16(v.y);
            __nv_bfloat16 hz = __float2bfloat16(v.z), hw = __float2bfloat16(v.w);
            __nv_bfloat162 h01(hx, hy), h23(hz, hw);
            __nv_bfloat162 l01(__float2bfloat16(v.x - __bfloat162float(hx)),
                               __float2bfloat16(v.y - __bfloat162float(hy)));
            __nv_bfloat162 l23(__float2bfloat16(v.z - __bfloat162float(hz)),
                               __float2bfloat16(v.w - __bfloat162float(hw)));
            *(uint2*)&sAhi[r * AST + c4] = make_uint2(*(uint32_t*)&h01, *(uint32_t*)&h23);
            *(uint2*)&sAlo[r * AST + c4] = make_uint2(*(uint32_t*)&l01, *(uint32_t*)&l23);
        }
#pragma unroll
        for (int it = 0; it < 2; it++) {
            int slot = tid + it * 256;
            int n = slot >> 2, q = slot & 3;
            *(uint4*)&sBhi[n * AST + q * 8] = bh[it];
            *(uint4*)&sBlo[n * AST + q * 8] = bl[it];
        }
        __syncthreads();
#pragma unroll
        for (int ks = 0; ks < 32; ks += 16) {
            uint32_t ahi[2][4], alo[2][4];
#pragma unroll
            for (int mf = 0; mf < 2; mf++) {
                uint32_t off = ((wm + mf * 16 + a_row) * AST + ks + a_kof) * 2;
                ldsm4(ahi[mf], uAhi + off);
                ldsm4(alo[mf], uAlo + off);
            }
#pragma unroll
            for (int np = 0; np < 4; np++) {
                uint32_t off = ((wn + np * 16 + b_row) * AST + ks + b_kof) * 2;
                uint32_t bhf[4], blf[4];
                ldsm4(bhf, uBhi + off);
                ldsm4(blf, uBlo + off);
#pragma unroll
                for (int mf = 0; mf < 2; mf++) {
                    mma_bf16(acc[mf][np * 2], ahi[mf], bhf);
                    mma_bf16(acc[mf][np * 2], ahi[mf], blf);
                    mma_bf16(acc[mf][np * 2], alo[mf], bhf);
                    mma_bf16(acc[mf][np * 2 + 1], ahi[mf], bhf + 2);
                    mma_bf16(acc[mf][np * 2 + 1], ahi[mf], blf + 2);
                    mma_bf16(acc[mf][np * 2 + 1], alo[mf], bhf + 2);
                }
            }
        }
    }
    int qr = lane >> 2, qc = (lane & 3) * 2;
#pragma unroll
    for (int mf = 0; mf < 2; mf++) {
        int r0 = m0 + wm + mf * 16 + qr;
#pragma unroll
        for (int nf = 0; nf < 8; nf++) {
            int cc = wn + nf * 8 + qc;
            if (r0 < M)
                *(float2*)(g_h1 + (size_t)r0 * 128 + cc) =
                    make_float2(acc[mf][nf][0], acc[mf][nf][1]);
            if (r0 + 8 < M)
                *(float2*)(g_h1 + (size_t)(r0 + 8) * 128 + cc) =
                    make_float2(acc[mf][nf][2], acc[mf][nf][3]);
        }
    }
}

// ---------------------------------------------------------------------------
// Layer-1 aggregation: warp-per-node CSR gather, fused self+bias+relu -> o1
// ---------------------------------------------------------------------------
__global__ __launch_bounds__(256) void k_agg1_gather(const float* __restrict__ b1, int N) {
    int node = (blockIdx.x * blockDim.x + threadIdx.x) >> 5;
    int lane = threadIdx.x & 31;
    if (node >= N) return;
    int s = g_rs[node], e = s + g_cnt[node];
    float d = g_dinv[node];
    const float* hr = g_h1 + (size_t)node * 128 + lane * 4;
    float4 acc = *(const float4*)hr;
    float dd = d * d;
    acc.x *= dd; acc.y *= dd; acc.z *= dd; acc.w *= dd;
    int t = s;
    for (; t + 1 < e; t += 2) {
        uint2 p0 = g_epay[t];
        uint2 p1 = g_epay[t + 1];
        float nr0 = __uint_as_float(p0.y);
        float nr1 = __uint_as_float(p1.y);
        float4 v0 = *(const float4*)(g_h1 + (size_t)p0.x * 128 + lane * 4);
        float4 v1 = *(const float4*)(g_h1 + (size_t)p1.x * 128 + lane * 4);
        acc.x += nr0 * v0.x + nr1 * v1.x;
        acc.y += nr0 * v0.y + nr1 * v1.y;
        acc.z += nr0 * v0.z + nr1 * v1.z;
        acc.w += nr0 * v0.w + nr1 * v1.w;
    }
    if (t < e) {
        uint2 p = g_epay[t];
        float nr = __uint_as_float(p.y);
        float4 v = *(const float4*)(g_h1 + (size_t)p.x * 128 + lane * 4);
        acc.x += nr * v.x; acc.y += nr * v.y; acc.z += nr * v.z; acc.w += nr * v.w;
    }
    float4 bb = *(const float4*)(b1 + lane * 4);
    acc.x = fmaxf(acc.x + bb.x, 0.f);
    acc.y = fmaxf(acc.y + bb.y, 0.f);
    acc.z = fmaxf(acc.z + bb.z, 0.f);
    acc.w = fmaxf(acc.w + bb.w, 0.f);
    *(float4*)(g_o1 + (size_t)node * 128 + lane * 4) = acc;
}

// ---------------------------------------------------------------------------
// GEMM2: h2[N,C] = o1[N,128] @ W2[128,C]
// ---------------------------------------------------------------------------
__global__ __launch_bounds__(128) void k_gemm2(const float* __restrict__ W2, int N, int C) {
    __shared__ float Ws[128 * C_CAP];
    for (int i = threadIdx.x; i < 128 * C; i += blockDim.x) Ws[i] = W2[i];
    __syncthreads();
    int warp = threadIdx.x >> 5;
    int lane = threadIdx.x & 31;
    int n = blockIdx.x * 4 + warp;
    if (n >= N) return;
    const float* xr = g_o1 + (size_t)n * 128;
    float a0 = 0.f, a1 = 0.f;
    int c1 = lane + 32;
#pragma unroll 4
    for (int k = 0; k < 128; k++) {
        float xv = xr[k];
        a0 += xv * Ws[k * C + lane];
        a1 += xv * Ws[k * C + (c1 < C ? c1 : 0)];
    }
    g_h2[(size_t)n * C + lane] = a0;
    if (c1 < C) g_h2[(size_t)n * C + c1] = a1;
}

// ---------------------------------------------------------------------------
// Layer-2: warp-per-node CSR gather + self + bias + log_softmax -> out
// ---------------------------------------------------------------------------
__global__ __launch_bounds__(256) void k_agg2_gather(float* __restrict__ out,
                                                     const float* __restrict__ b2,
                                                     int N, int C) {
    int node = (blockIdx.x * blockDim.x + threadIdx.x) >> 5;
    int lane = threadIdx.x & 31;
    if (node >= N) return;
    int s = g_rs[node], e = s + g_cnt[node];
    float d = g_dinv[node];
    float dd = d * d;
    int c1 = lane + 32;
    bool has1 = c1 < C;
    const float* h0 = g_h2 + (size_t)node * C;
    float a0 = dd * h0[lane];
    float a1 = has1 ? dd * h0[c1] : 0.f;
    for (int t = s; t < e; t++) {
        uint2 p = g_epay[t];
        float nr = __uint_as_float(p.y);
        const float* hp = g_h2 + (size_t)p.x * C;
        a0 += nr * hp[lane];
        if (has1) a1 += nr * hp[c1];
    }
    a0 += b2[lane];
    if (has1) a1 += b2[c1];
    const float NEG_INF = __int_as_float(0xff800000);
    float v1 = has1 ? a1 : NEG_INF;
    float m = fmaxf(a0, v1);
#pragma unroll
    for (int o = 16; o > 0; o >>= 1) m = fmaxf(m, __shfl_xor_sync(0xffffffffu, m, o));
    float sum = expf(a0 - m) + (has1 ? expf(a1 - m) : 0.f);
#pragma unroll
    for (int o = 16; o > 0; o >>= 1) sum += __shfl_xor_sync(0xffffffffu, sum, o);
    float l = logf(sum);
    float* z = out + (size_t)node * C;
    z[lane] = a0 - m - l;
    if (has1) z[c1] = a1 - m - l;
}

// ---------------------------------------------------------------------------
extern "C" void kernel_launch(void* const* d_in, const int* in_sizes, int n_in,
                              void* d_out, int out_size) {
    const float* feat = (const float*)d_in[0];
    const void*  ei   = d_in[1];
    const float* ew   = (const float*)d_in[2];
    const float* W1   = (const float*)d_in[3];
    const float* b1   = (const float*)d_in[4];
    const float* W2   = (const float*)d_in[5];
    const float* b2   = (const float*)d_in[6];
    float* out = (float*)d_out;

    int H   = in_sizes[4];
    int FIN = in_sizes[3] / H;
    int N   = in_sizes[0] / FIN;
    int C   = in_sizes[6];
    int E   = in_sizes[2];
    (void)n_in; (void)out_size;

    k_detect<<<1, 256>>>((const unsigned int*)ei, (long long)2 * E);
    k_deg_init<<<(N + 255) / 256, 256>>>(N);
    k_deg_count<<<(E + 255) / 256, 256>>>(ei, ew, E);
    k_rsqrt<<<(N + 255) / 256, 256>>>(N);
    k_scan<<<1, 1024>>>(N);
    k_fill<<<(E + 255) / 256, 256>>>(ei, ew, E);

    k_prepB<<<(FIN * 128 + 255) / 256, 256>>>(W1, FIN);
    k_gemm1_mma<<<(N + 127) / 128, 256>>>(feat, N, FIN);

    k_agg1_gather<<<(N + 7) / 8, 256>>>(b1, N);
    k_gemm2<<<(N + 3) / 4, 128>>>(W2, N, C);
    k_agg2_gather<<<(N + 7) / 8, 256>>>(out, b2, N, C);
}

// round 6
// speedup vs baseline: 2.0508x; 1.1197x over previous
#include <cuda_runtime.h>
#include <cuda_bf16.h>
#include <stdint.h>

#define N_CAP 50000
#define E_CAP 1000000
#define H_CAP 128
#define C_CAP 64
#define KMAX  512

__device__ float g_dinv[N_CAP];
__device__ int   g_cnt[N_CAP];
__device__ int   g_rs[N_CAP];
__device__ int   g_cur[N_CAP];
__device__ uint2 g_epay[E_CAP];
__device__ float g_h1[(size_t)N_CAP * H_CAP];
__device__ float g_o1[(size_t)N_CAP * H_CAP];
__device__ float g_h2[(size_t)N_CAP * C_CAP];
__device__ int   g_is64;
__device__ __nv_bfloat16 g_Bhi[H_CAP * KMAX];
__device__ __nv_bfloat16 g_Blo[H_CAP * KMAX];

// ---------------------------------------------------------------------------
__device__ __forceinline__ void edge_rc(const void* ei, int is64, long long E,
                                        long long e, int& r, int& c) {
    if (is64) {
        const long long* p = (const long long*)ei;
        r = (int)p[e]; c = (int)p[E + e];
    } else {
        const int* p = (const int*)ei;
        r = p[e]; c = p[E + e];
    }
}

// init dinv/cnt for all nodes; block 0 additionally detects edge dtype
__global__ void k_init_detect(const unsigned int* p, long long n32, int N) {
    int i = blockIdx.x * blockDim.x + threadIdx.x;
    if (i < N) { g_dinv[i] = 1.0f; g_cnt[i] = 0; }
    if (blockIdx.x == 0) {
        __shared__ unsigned int s;
        if (threadIdx.x == 0) s = 0u;
        __syncthreads();
        unsigned int v = 0u;
        long long lim = n32 < 16384 ? n32 : 16384;
        for (long long j = 1 + 2 * (long long)threadIdx.x; j < lim; j += 2 * (long long)blockDim.x)
            v |= p[j];
        atomicOr(&s, v);
        __syncthreads();
        if (threadIdx.x == 0) g_is64 = (s == 0u) ? 1 : 0;
    }
}

__global__ void k_deg_count(const void* ei, const float* __restrict__ w, int E) {
    int e = blockIdx.x * blockDim.x + threadIdx.x;
    if (e < E) {
        int r, c;
        edge_rc(ei, g_is64, E, e, r, c);
        atomicAdd(&g_dinv[c], w[e]);
        atomicAdd(&g_cnt[c], 1);
    }
}
__global__ void k_rsqrt(int N) {
    int i = blockIdx.x * blockDim.x + threadIdx.x;
    if (i < N) g_dinv[i] = rsqrtf(g_dinv[i]);
}

// ---------------------------------------------------------------------------
// exclusive scan (warp-shuffle), single block 1024 threads
// ---------------------------------------------------------------------------
__global__ __launch_bounds__(1024) void k_scan(int N) {
    __shared__ int wsum[32];
    __shared__ int run;
    int tid = threadIdx.x, lane = tid & 31, w = tid >> 5;
    if (tid == 0) run = 0;
    __syncthreads();
    for (int base = 0; base < N; base += 1024) {
        int idx = base + tid;
        int v = (idx < N) ? g_cnt[idx] : 0;
        int x = v;
#pragma unroll
        for (int o = 1; o < 32; o <<= 1) {
            int t = __shfl_up_sync(0xffffffffu, x, o);
            if (lane >= o) x += t;
        }
        if (lane == 31) wsum[w] = x;
        __syncthreads();
        if (w == 0) {
            int s = wsum[lane];
#pragma unroll
            for (int o = 1; o < 32; o <<= 1) {
                int t = __shfl_up_sync(0xffffffffu, s, o);
                if (lane >= o) s += t;
            }
            wsum[lane] = s;
        }
        __syncthreads();
        int excl = x - v + (w ? wsum[w - 1] : 0) + run;
        if (idx < N) { g_rs[idx] = excl; g_cur[idx] = excl; }
        __syncthreads();
        if (tid == 0) run += wsum[31];
        __syncthreads();
    }
}

__global__ void k_fill(const void* ei, const float* __restrict__ w, int E) {
    int e = blockIdx.x * blockDim.x + threadIdx.x;
    if (e < E) {
        int r, c;
        edge_rc(ei, g_is64, E, e, r, c);
        float nr = g_dinv[r] * w[e] * g_dinv[c];
        int pos = atomicAdd(&g_cur[c], 1);
        g_epay[pos] = make_uint2((unsigned)r, __float_as_uint(nr));
    }
}

// ---------------------------------------------------------------------------
__global__ void k_prepB(const float* __restrict__ W1, int K) {
    int idx = blockIdx.x * blockDim.x + threadIdx.x;
    if (idx >= K * 128) return;
    int k = idx >> 7, n = idx & 127;
    float x = W1[(size_t)k * 128 + n];
    __nv_bfloat16 h = __float2bfloat16(x);
    __nv_bfloat16 l = __float2bfloat16(x - __bfloat162float(h));
    g_Bhi[(size_t)n * K + k] = h;
    g_Blo[(size_t)n * K + k] = l;
}

// ---------------------------------------------------------------------------
// GEMM1: 128x128 block, bf16-split mma.sync
// ---------------------------------------------------------------------------
#define AST 40

__device__ __forceinline__ void mma_bf16(float* c, const uint32_t* a, const uint32_t* b) {
    asm volatile(
        "mma.sync.aligned.m16n8k16.row.col.f32.bf16.bf16.f32 "
        "{%0,%1,%2,%3}, {%4,%5,%6,%7}, {%8,%9}, {%0,%1,%2,%3};"
        : "+f"(c[0]), "+f"(c[1]), "+f"(c[2]), "+f"(c[3])
        : "r"(a[0]), "r"(a[1]), "r"(a[2]), "r"(a[3]), "r"(b[0]), "r"(b[1]));
}
__device__ __forceinline__ void ldsm4(uint32_t* r, uint32_t addr) {
    asm volatile("ldmatrix.sync.aligned.m8n8.x4.shared.b16 {%0,%1,%2,%3}, [%4];"
                 : "=r"(r[0]), "=r"(r[1]), "=r"(r[2]), "=r"(r[3]) : "r"(addr));
}

__global__ __launch_bounds__(256, 1) void k_gemm1_mma(const float* __restrict__ A,
                                                      int M, int K) {
    __shared__ __nv_bfloat16 sAhi[128 * AST];
    __shared__ __nv_bfloat16 sAlo[128 * AST];
    __shared__ __nv_bfloat16 sBhi[128 * AST];
    __shared__ __nv_bfloat16 sBlo[128 * AST];

    int tid = threadIdx.x, wid = tid >> 5, lane = tid & 31;
    int m0 = blockIdx.x * 128;
    int wm = (wid & 3) * 32;
    int wn = (wid >> 2) * 64;

    uint32_t uAhi = (uint32_t)__cvta_generic_to_shared(sAhi);
    uint32_t uAlo = (uint32_t)__cvta_generic_to_shared(sAlo);
    uint32_t uBhi = (uint32_t)__cvta_generic_to_shared(sBhi);
    uint32_t uBlo = (uint32_t)__cvta_generic_to_shared(sBlo);

    float acc[2][8][4];
#pragma unroll
    for (int i = 0; i < 2; i++)
#pragma unroll
        for (int j = 0; j < 8; j++)
#pragma unroll
            for (int q = 0; q < 4; q++) acc[i][j][q] = 0.0f;

    int a_row = (lane & 7) + ((lane >> 3) & 1) * 8;
    int a_kof = (lane >> 4) * 8;
    int b_row = (lane & 7) + ((lane >> 4) ? 8 : 0);
    int b_kof = ((lane >> 3) & 1) * 8;

    int ktiles = K >> 5;
    for (int kt = 0; kt < ktiles; kt++) {
        int k0 = kt << 5;
        float4 av[4];
#pragma unroll
        for (int it = 0; it < 4; it++) {
            int slot = tid + it * 256;
            int r = slot >> 3, c4 = (slot & 7) << 2;
            int gr = m0 + r;
            av[it] = make_float4(0.f, 0.f, 0.f, 0.f);
            if (gr < M) av[it] = *(const float4*)(A + (size_t)gr * K + k0 + c4);
        }
        uint4 bh[2], bl[2];
#pragma unroll
        for (int it = 0; it < 2; it++) {
            int slot = tid + it * 256;
            int n = slot >> 2, q = slot & 3;
            bh[it] = *(const uint4*)(g_Bhi + (size_t)n * K + k0 + q * 8);
            bl[it] = *(const uint4*)(g_Blo + (size_t)n * K + k0 + q * 8);
        }
        __syncthreads();
#pragma unroll
        for (int it = 0; it < 4; it++) {
            int slot = tid + it * 256;
            int r = slot >> 3, c4 = (slot & 7) << 2;
            float4 v = av[it];
            __nv_bfloat16 hx = __float2bfloat16(v.x), hy = __float2bfloat16(v.y);
            __nv_bfloat16 hz = __float2bfloat16(v.z), hw = __float2bfloat16(v.w);
            __nv_bfloat162 h01(hx, hy), h23(hz, hw);
            __nv_bfloat162 l01(__float2bfloat16(v.x - __bfloat162float(hx)),
                               __float2bfloat16(v.y - __bfloat162float(hy)));
            __nv_bfloat162 l23(__float2bfloat16(v.z - __bfloat162float(hz)),
                               __float2bfloat16(v.w - __bfloat162float(hw)));
            *(uint2*)&sAhi[r * AST + c4] = make_uint2(*(uint32_t*)&h01, *(uint32_t*)&h23);
            *(uint2*)&sAlo[r * AST + c4] = make_uint2(*(uint32_t*)&l01, *(uint32_t*)&l23);
        }
#pragma unroll
        for (int it = 0; it < 2; it++) {
            int slot = tid + it * 256;
            int n = slot >> 2, q = slot & 3;
            *(uint4*)&sBhi[n * AST + q * 8] = bh[it];
            *(uint4*)&sBlo[n * AST + q * 8] = bl[it];
        }
        __syncthreads();
#pragma unroll
        for (int ks = 0; ks < 32; ks += 16) {
            uint32_t ahi[2][4], alo[2][4];
#pragma unroll
            for (int mf = 0; mf < 2; mf++) {
                uint32_t off = ((wm + mf * 16 + a_row) * AST + ks + a_kof) * 2;
                ldsm4(ahi[mf], uAhi + off);
                ldsm4(alo[mf], uAlo + off);
            }
#pragma unroll
            for (int np = 0; np < 4; np++) {
                uint32_t off = ((wn + np * 16 + b_row) * AST + ks + b_kof) * 2;
                uint32_t bhf[4], blf[4];
                ldsm4(bhf, uBhi + off);
                ldsm4(blf, uBlo + off);
#pragma unroll
                for (int mf = 0; mf < 2; mf++) {
                    mma_bf16(acc[mf][np * 2], ahi[mf], bhf);
                    mma_bf16(acc[mf][np * 2], ahi[mf], blf);
                    mma_bf16(acc[mf][np * 2], alo[mf], bhf);
                    mma_bf16(acc[mf][np * 2 + 1], ahi[mf], bhf + 2);
                    mma_bf16(acc[mf][np * 2 + 1], ahi[mf], blf + 2);
                    mma_bf16(acc[mf][np * 2 + 1], alo[mf], bhf + 2);
                }
            }
        }
    }
    int qr = lane >> 2, qc = (lane & 3) * 2;
#pragma unroll
    for (int mf = 0; mf < 2; mf++) {
        int r0 = m0 + wm + mf * 16 + qr;
#pragma unroll
        for (int nf = 0; nf < 8; nf++) {
            int cc = wn + nf * 8 + qc;
            if (r0 < M)
                *(float2*)(g_h1 + (size_t)r0 * 128 + cc) =
                    make_float2(acc[mf][nf][0], acc[mf][nf][1]);
            if (r0 + 8 < M)
                *(float2*)(g_h1 + (size_t)(r0 + 8) * 128 + cc) =
                    make_float2(acc[mf][nf][2], acc[mf][nf][3]);
        }
    }
}

// ---------------------------------------------------------------------------
// Layer-1: warp-per-node CSR gather (MLP-4), fused self+bias+relu -> o1
// ---------------------------------------------------------------------------
__global__ __launch_bounds__(256) void k_agg1_gather(const float* __restrict__ b1, int N) {
    int node = (blockIdx.x * blockDim.x + threadIdx.x) >> 5;
    int lane = threadIdx.x & 31;
    if (node >= N) return;
    int s = g_rs[node], e = s + g_cnt[node];
    float d = g_dinv[node];
    float4 acc = *(const float4*)(g_h1 + (size_t)node * 128 + lane * 4);
    float dd = d * d;
    acc.x *= dd; acc.y *= dd; acc.z *= dd; acc.w *= dd;
    int t = s;
    for (; t + 4 <= e; t += 4) {
        uint2 p0 = g_epay[t], p1 = g_epay[t + 1], p2 = g_epay[t + 2], p3 = g_epay[t + 3];
        float4 v0 = *(const float4*)(g_h1 + (size_t)p0.x * 128 + lane * 4);
        float4 v1 = *(const float4*)(g_h1 + (size_t)p1.x * 128 + lane * 4);
        float4 v2 = *(const float4*)(g_h1 + (size_t)p2.x * 128 + lane * 4);
        float4 v3 = *(const float4*)(g_h1 + (size_t)p3.x * 128 + lane * 4);
        float n0 = __uint_as_float(p0.y), n1 = __uint_as_float(p1.y);
        float n2 = __uint_as_float(p2.y), n3 = __uint_as_float(p3.y);
        acc.x += n0 * v0.x + n1 * v1.x + n2 * v2.x + n3 * v3.x;
        acc.y += n0 * v0.y + n1 * v1.y + n2 * v2.y + n3 * v3.y;
        acc.z += n0 * v0.z + n1 * v1.z + n2 * v2.z + n3 * v3.z;
        acc.w += n0 * v0.w + n1 * v1.w + n2 * v2.w + n3 * v3.w;
    }
    for (; t < e; t++) {
        uint2 p = g_epay[t];
        float nr = __uint_as_float(p.y);
        float4 v = *(const float4*)(g_h1 + (size_t)p.x * 128 + lane * 4);
        acc.x += nr * v.x; acc.y += nr * v.y; acc.z += nr * v.z; acc.w += nr * v.w;
    }
    float4 bb = *(const float4*)(b1 + lane * 4);
    acc.x = fmaxf(acc.x + bb.x, 0.f);
    acc.y = fmaxf(acc.y + bb.y, 0.f);
    acc.z = fmaxf(acc.z + bb.z, 0.f);
    acc.w = fmaxf(acc.w + bb.w, 0.f);
    *(float4*)(g_o1 + (size_t)node * 128 + lane * 4) = acc;
}

// ---------------------------------------------------------------------------
__global__ __launch_bounds__(128) void k_gemm2(const float* __restrict__ W2, int N, int C) {
    __shared__ float Ws[128 * C_CAP];
    for (int i = threadIdx.x; i < 128 * C; i += blockDim.x) Ws[i] = W2[i];
    __syncthreads();
    int warp = threadIdx.x >> 5;
    int lane = threadIdx.x & 31;
    int n = blockIdx.x * 4 + warp;
    if (n >= N) return;
    const float* xr = g_o1 + (size_t)n * 128;
    float a0 = 0.f, a1 = 0.f;
    int c1 = lane + 32;
#pragma unroll 4
    for (int k = 0; k < 128; k++) {
        float xv = xr[k];
        a0 += xv * Ws[k * C + lane];
        a1 += xv * Ws[k * C + (c1 < C ? c1 : 0)];
    }
    g_h2[(size_t)n * C + lane] = a0;
    if (c1 < C) g_h2[(size_t)n * C + c1] = a1;
}

// ---------------------------------------------------------------------------
// Layer-2: warp-per-node gather (MLP-2) + self + bias + log_softmax -> out
// ---------------------------------------------------------------------------
__global__ __launch_bounds__(256) void k_agg2_gather(float* __restrict__ out,
                                                     const float* __restrict__ b2,
                                                     int N, int C) {
    int node = (blockIdx.x * blockDim.x + threadIdx.x) >> 5;
    int lane = threadIdx.x & 31;
    if (node >= N) return;
    int s = g_rs[node], e = s + g_cnt[node];
    float d = g_dinv[node];
    float dd = d * d;
    int c1 = lane + 32;
    bool has1 = c1 < C;
    const float* h0 = g_h2 + (size_t)node * C;
    float a0 = dd * h0[lane];
    float a1 = has1 ? dd * h0[c1] : 0.f;
    int t = s;
    for (; t + 2 <= e; t += 2) {
        uint2 p0 = g_epay[t], p1 = g_epay[t + 1];
        const float* hp0 = g_h2 + (size_t)p0.x * C;
        const float* hp1 = g_h2 + (size_t)p1.x * C;
        float n0 = __uint_as_float(p0.y), n1 = __uint_as_float(p1.y);
        a0 += n0 * hp0[lane] + n1 * hp1[lane];
        if (has1) a1 += n0 * hp0[c1] + n1 * hp1[c1];
    }
    for (; t < e; t++) {
        uint2 p = g_epay[t];
        float nr = __uint_as_float(p.y);
        const float* hp = g_h2 + (size_t)p.x * C;
        a0 += nr * hp[lane];
        if (has1) a1 += nr * hp[c1];
    }
    a0 += b2[lane];
    if (has1) a1 += b2[c1];
    const float NEG_INF = __int_as_float(0xff800000);
    float v1 = has1 ? a1 : NEG_INF;
    float m = fmaxf(a0, v1);
#pragma unroll
    for (int o = 16; o > 0; o >>= 1) m = fmaxf(m, __shfl_xor_sync(0xffffffffu, m, o));
    float sum = expf(a0 - m) + (has1 ? expf(a1 - m) : 0.f);
#pragma unroll
    for (int o = 16; o > 0; o >>= 1) sum += __shfl_xor_sync(0xffffffffu, sum, o);
    float l = logf(sum);
    float* z = out + (size_t)node * C;
    z[lane] = a0 - m - l;
    if (has1) z[c1] = a1 - m - l;
}

// ---------------------------------------------------------------------------
extern "C" void kernel_launch(void* const* d_in, const int* in_sizes, int n_in,
                              void* d_out, int out_size) {
    const float* feat = (const float*)d_in[0];
    const void*  ei   = d_in[1];
    const float* ew   = (const float*)d_in[2];
    const float* W1   = (const float*)d_in[3];
    const float* b1   = (const float*)d_in[4];
    const float* W2   = (const float*)d_in[5];
    const float* b2   = (const float*)d_in[6];
    float* out = (float*)d_out;

    int H   = in_sizes[4];
    int FIN = in_sizes[3] / H;
    int N   = in_sizes[0] / FIN;
    int C   = in_sizes[6];
    int E   = in_sizes[2];
    (void)n_in; (void)out_size;

    k_init_detect<<<(N + 255) / 256, 256>>>((const unsigned int*)ei, (long long)2 * E, N);
    k_deg_count<<<(E + 255) / 256, 256>>>(ei, ew, E);
    k_rsqrt<<<(N + 255) / 256, 256>>>(N);
    k_scan<<<1, 1024>>>(N);
    k_fill<<<(E + 255) / 256, 256>>>(ei, ew, E);

    k_prepB<<<(FIN * 128 + 255) / 256, 256>>>(W1, FIN);
    k_gemm1_mma<<<(N + 127) / 128, 256>>>(feat, N, FIN);

    k_agg1_gather<<<(N + 7) / 8, 256>>>(b1, N);
    k_gemm2<<<(N + 3) / 4, 128>>>(W2, N, C);
    k_agg2_gather<<<(N + 7) / 8, 256>>>(out, b2, N, C);
}

// round 7
// speedup vs baseline: 2.2829x; 1.1132x over previous
#include <cuda_runtime.h>
#include <cuda_bf16.h>
#include <stdint.h>

#define N_CAP 50000
#define E_CAP 1000000
#define H_CAP 128
#define C_CAP 64
#define KMAX  512

__device__ float g_dinv[N_CAP];
__device__ int   g_cnt[N_CAP];
__device__ int   g_rs[N_CAP];
__device__ int   g_cur[N_CAP];
__device__ int   g_bsum[64];
__device__ uint2 g_epay[E_CAP];
__device__ float g_h1[(size_t)N_CAP * H_CAP];
__device__ float g_o1[(size_t)N_CAP * H_CAP];
__device__ float g_h2[(size_t)N_CAP * C_CAP];
__device__ int   g_is64;
__device__ __nv_bfloat16 g_Bhi[H_CAP * KMAX];
__device__ __nv_bfloat16 g_Blo[H_CAP * KMAX];

// ---------------------------------------------------------------------------
__device__ __forceinline__ void edge_rc(const void* ei, int is64, long long E,
                                        long long e, int& r, int& c) {
    if (is64) {
        const long long* p = (const long long*)ei;
        r = (int)p[e]; c = (int)p[E + e];
    } else {
        const int* p = (const int*)ei;
        r = p[e]; c = p[E + e];
    }
}

// init dinv/cnt for all nodes; block 0 additionally detects edge dtype
__global__ void k_init_detect(const unsigned int* p, long long n32, int N) {
    int i = blockIdx.x * blockDim.x + threadIdx.x;
    if (i < N) { g_dinv[i] = 1.0f; g_cnt[i] = 0; }
    if (blockIdx.x == 0) {
        __shared__ unsigned int s;
        if (threadIdx.x == 0) s = 0u;
        __syncthreads();
        unsigned int v = 0u;
        long long lim = n32 < 16384 ? n32 : 16384;
        for (long long j = 1 + 2 * (long long)threadIdx.x; j < lim; j += 2 * (long long)blockDim.x)
            v |= p[j];
        atomicOr(&s, v);
        __syncthreads();
        if (threadIdx.x == 0) g_is64 = (s == 0u) ? 1 : 0;
    }
}

__global__ void k_deg_count(const void* ei, const float* __restrict__ w, int E) {
    int e = blockIdx.x * blockDim.x + threadIdx.x;
    if (e < E) {
        int r, c;
        edge_rc(ei, g_is64, E, e, r, c);
        atomicAdd(&g_dinv[c], w[e]);
        atomicAdd(&g_cnt[c], 1);
    }
}

// ---------------------------------------------------------------------------
// Scan phase 1: per-block exclusive scan of g_cnt chunk -> g_rs (block-local),
// block total -> g_bsum.  Also fuses dinv = rsqrt(dinv).
// ---------------------------------------------------------------------------
__global__ __launch_bounds__(1024) void k_scan1(int N) {
    __shared__ int wsum[32];
    int tid = threadIdx.x, lane = tid & 31, w = tid >> 5;
    int idx = blockIdx.x * 1024 + tid;
    int v = (idx < N) ? g_cnt[idx] : 0;
    int x = v;
#pragma unroll
    for (int o = 1; o < 32; o <<= 1) {
        int t = __shfl_up_sync(0xffffffffu, x, o);
        if (lane >= o) x += t;
    }
    if (lane == 31) wsum[w] = x;
    __syncthreads();
    if (w == 0) {
        int s = wsum[lane];
#pragma unroll
        for (int o = 1; o < 32; o <<= 1) {
            int t = __shfl_up_sync(0xffffffffu, s, o);
            if (lane >= o) s += t;
        }
        wsum[lane] = s;
    }
    __syncthreads();
    int excl = x - v + (w ? wsum[w - 1] : 0);
    if (idx < N) {
        g_rs[idx] = excl;
        g_dinv[idx] = rsqrtf(g_dinv[idx]);
    }
    if (tid == 1023) g_bsum[blockIdx.x] = excl + v;
}

// Scan phase 2: add prefix of block sums; finalize g_rs/g_cur.
__global__ __launch_bounds__(1024) void k_scan2(int N) {
    __shared__ int off;
    int tid = threadIdx.x;
    if (tid == 0) {
        int s = 0;
        for (int b = 0; b < blockIdx.x; b++) s += g_bsum[b];
        off = s;
    }
    __syncthreads();
    int idx = blockIdx.x * 1024 + tid;
    if (idx < N) {
        int v = g_rs[idx] + off;
        g_rs[idx] = v;
        g_cur[idx] = v;
    }
}

__global__ void k_fill(const void* ei, const float* __restrict__ w, int E) {
    int e = blockIdx.x * blockDim.x + threadIdx.x;
    if (e < E) {
        int r, c;
        edge_rc(ei, g_is64, E, e, r, c);
        float nr = g_dinv[r] * w[e] * g_dinv[c];
        int pos = atomicAdd(&g_cur[c], 1);
        g_epay[pos] = make_uint2((unsigned)r, __float_as_uint(nr));
    }
}

// ---------------------------------------------------------------------------
__global__ void k_prepB(const float* __restrict__ W1, int K) {
    int idx = blockIdx.x * blockDim.x + threadIdx.x;
    if (idx >= K * 128) return;
    int k = idx >> 7, n = idx & 127;
    float x = W1[(size_t)k * 128 + n];
    __nv_bfloat16 h = __float2bfloat16(x);
    __nv_bfloat16 l = __float2bfloat16(x - __bfloat162float(h));
    g_Bhi[(size_t)n * K + k] = h;
    g_Blo[(size_t)n * K + k] = l;
}

// ---------------------------------------------------------------------------
// GEMM1: 128x128 block, bf16-split mma.sync
// ---------------------------------------------------------------------------
#define AST 40

__device__ __forceinline__ void mma_bf16(float* c, const uint32_t* a, const uint32_t* b) {
    asm volatile(
        "mma.sync.aligned.m16n8k16.row.col.f32.bf16.bf16.f32 "
        "{%0,%1,%2,%3}, {%4,%5,%6,%7}, {%8,%9}, {%0,%1,%2,%3};"
        : "+f"(c[0]), "+f"(c[1]), "+f"(c[2]), "+f"(c[3])
        : "r"(a[0]), "r"(a[1]), "r"(a[2]), "r"(a[3]), "r"(b[0]), "r"(b[1]));
}
__device__ __forceinline__ void ldsm4(uint32_t* r, uint32_t addr) {
    asm volatile("ldmatrix.sync.aligned.m8n8.x4.shared.b16 {%0,%1,%2,%3}, [%4];"
                 : "=r"(r[0]), "=r"(r[1]), "=r"(r[2]), "=r"(r[3]) : "r"(addr));
}

__global__ __launch_bounds__(256, 1) void k_gemm1_mma(const float* __restrict__ A,
                                                      int M, int K) {
    __shared__ __nv_bfloat16 sAhi[128 * AST];
    __shared__ __nv_bfloat16 sAlo[128 * AST];
    __shared__ __nv_bfloat16 sBhi[128 * AST];
    __shared__ __nv_bfloat16 sBlo[128 * AST];

    int tid = threadIdx.x, wid = tid >> 5, lane = tid & 31;
    int m0 = blockIdx.x * 128;
    int wm = (wid & 3) * 32;
    int wn = (wid >> 2) * 64;

    uint32_t uAhi = (uint32_t)__cvta_generic_to_shared(sAhi);
    uint32_t uAlo = (uint32_t)__cvta_generic_to_shared(sAlo);
    uint32_t uBhi = (uint32_t)__cvta_generic_to_shared(sBhi);
    uint32_t uBlo = (uint32_t)__cvta_generic_to_shared(sBlo);

    float acc[2][8][4];
#pragma unroll
    for (int i = 0; i < 2; i++)
#pragma unroll
        for (int j = 0; j < 8; j++)
#pragma unroll
            for (int q = 0; q < 4; q++) acc[i][j][q] = 0.0f;

    int a_row = (lane & 7) + ((lane >> 3) & 1) * 8;
    int a_kof = (lane >> 4) * 8;
    int b_row = (lane & 7) + ((lane >> 4) ? 8 : 0);
    int b_kof = ((lane >> 3) & 1) * 8;

    int ktiles = K >> 5;
    for (int kt = 0; kt < ktiles; kt++) {
        int k0 = kt << 5;
        float4 av[4];
#pragma unroll
        for (int it = 0; it < 4; it++) {
            int slot = tid + it * 256;
            int r = slot >> 3, c4 = (slot & 7) << 2;
            int gr = m0 + r;
            av[it] = make_float4(0.f, 0.f, 0.f, 0.f);
            if (gr < M) av[it] = *(const float4*)(A + (size_t)gr * K + k0 + c4);
        }
        uint4 bh[2], bl[2];
#pragma unroll
        for (int it = 0; it < 2; it++) {
            int slot = tid + it * 256;
            int n = slot >> 2, q = slot & 3;
            bh[it] = *(const uint4*)(g_Bhi + (size_t)n * K + k0 + q * 8);
            bl[it] = *(const uint4*)(g_Blo + (size_t)n * K + k0 + q * 8);
        }
        __syncthreads();
#pragma unroll
        for (int it = 0; it < 4; it++) {
            int slot = tid + it * 256;
            int r = slot >> 3, c4 = (slot & 7) << 2;
            float4 v = av[it];
            __nv_bfloat16 hx = __float2bfloat16(v.x), hy = __float2bfloat16(v.y);
            __nv_bfloat16 hz = __float2bfloat16(v.z), hw = __float2bfloat16(v.w);
            __nv_bfloat162 h01(hx, hy), h23(hz, hw);
            __nv_bfloat162 l01(__float2bfloat16(v.x - __bfloat162float(hx)),
                               __float2bfloat16(v.y - __bfloat162float(hy)));
            __nv_bfloat162 l23(__float2bfloat16(v.z - __bfloat162float(hz)),
                               __float2bfloat16(v.w - __bfloat162float(hw)));
            *(uint2*)&sAhi[r * AST + c4] = make_uint2(*(uint32_t*)&h01, *(uint32_t*)&h23);
            *(uint2*)&sAlo[r * AST + c4] = make_uint2(*(uint32_t*)&l01, *(uint32_t*)&l23);
        }
#pragma unroll
        for (int it = 0; it < 2; it++) {
            int slot = tid + it * 256;
            int n = slot >> 2, q = slot & 3;
            *(uint4*)&sBhi[n * AST + q * 8] = bh[it];
            *(uint4*)&sBlo[n * AST + q * 8] = bl[it];
        }
        __syncthreads();
#pragma unroll
        for (int ks = 0; ks < 32; ks += 16) {
            uint32_t ahi[2][4], alo[2][4];
#pragma unroll
            for (int mf = 0; mf < 2; mf++) {
                uint32_t off = ((wm + mf * 16 + a_row) * AST + ks + a_kof) * 2;
                ldsm4(ahi[mf], uAhi + off);
                ldsm4(alo[mf], uAlo + off);
            }
#pragma unroll
            for (int np = 0; np < 4; np++) {
                uint32_t off = ((wn + np * 16 + b_row) * AST + ks + b_kof) * 2;
                uint32_t bhf[4], blf[4];
                ldsm4(bhf, uBhi + off);
                ldsm4(blf, uBlo + off);
#pragma unroll
                for (int mf = 0; mf < 2; mf++) {
                    mma_bf16(acc[mf][np * 2], ahi[mf], bhf);
                    mma_bf16(acc[mf][np * 2], ahi[mf], blf);
                    mma_bf16(acc[mf][np * 2], alo[mf], bhf);
                    mma_bf16(acc[mf][np * 2 + 1], ahi[mf], bhf + 2);
                    mma_bf16(acc[mf][np * 2 + 1], ahi[mf], blf + 2);
                    mma_bf16(acc[mf][np * 2 + 1], alo[mf], bhf + 2);
                }
            }
        }
    }
    int qr = lane >> 2, qc = (lane & 3) * 2;
#pragma unroll
    for (int mf = 0; mf < 2; mf++) {
        int r0 = m0 + wm + mf * 16 + qr;
#pragma unroll
        for (int nf = 0; nf < 8; nf++) {
            int cc = wn + nf * 8 + qc;
            if (r0 < M)
                *(float2*)(g_h1 + (size_t)r0 * 128 + cc) =
                    make_float2(acc[mf][nf][0], acc[mf][nf][1]);
            if (r0 + 8 < M)
                *(float2*)(g_h1 + (size_t)(r0 + 8) * 128 + cc) =
                    make_float2(acc[mf][nf][2], acc[mf][nf][3]);
        }
    }
}

// ---------------------------------------------------------------------------
// Layer-1: warp-per-node CSR gather (MLP-4), fused self+bias+relu -> o1
// ---------------------------------------------------------------------------
__global__ __launch_bounds__(256) void k_agg1_gather(const float* __restrict__ b1, int N) {
    int node = (blockIdx.x * blockDim.x + threadIdx.x) >> 5;
    int lane = threadIdx.x & 31;
    if (node >= N) return;
    int s = g_rs[node], e = s + g_cnt[node];
    float d = g_dinv[node];
    float4 acc = *(const float4*)(g_h1 + (size_t)node * 128 + lane * 4);
    float dd = d * d;
    acc.x *= dd; acc.y *= dd; acc.z *= dd; acc.w *= dd;
    int t = s;
    for (; t + 4 <= e; t += 4) {
        uint2 p0 = g_epay[t], p1 = g_epay[t + 1], p2 = g_epay[t + 2], p3 = g_epay[t + 3];
        float4 v0 = *(const float4*)(g_h1 + (size_t)p0.x * 128 + lane * 4);
        float4 v1 = *(const float4*)(g_h1 + (size_t)p1.x * 128 + lane * 4);
        float4 v2 = *(const float4*)(g_h1 + (size_t)p2.x * 128 + lane * 4);
        float4 v3 = *(const float4*)(g_h1 + (size_t)p3.x * 128 + lane * 4);
        float n0 = __uint_as_float(p0.y), n1 = __uint_as_float(p1.y);
        float n2 = __uint_as_float(p2.y), n3 = __uint_as_float(p3.y);
        acc.x += n0 * v0.x + n1 * v1.x + n2 * v2.x + n3 * v3.x;
        acc.y += n0 * v0.y + n1 * v1.y + n2 * v2.y + n3 * v3.y;
        acc.z += n0 * v0.z + n1 * v1.z + n2 * v2.z + n3 * v3.z;
        acc.w += n0 * v0.w + n1 * v1.w + n2 * v2.w + n3 * v3.w;
    }
    for (; t < e; t++) {
        uint2 p = g_epay[t];
        float nr = __uint_as_float(p.y);
        float4 v = *(const float4*)(g_h1 + (size_t)p.x * 128 + lane * 4);
        acc.x += nr * v.x; acc.y += nr * v.y; acc.z += nr * v.z; acc.w += nr * v.w;
    }
    float4 bb = *(const float4*)(b1 + lane * 4);
    acc.x = fmaxf(acc.x + bb.x, 0.f);
    acc.y = fmaxf(acc.y + bb.y, 0.f);
    acc.z = fmaxf(acc.z + bb.z, 0.f);
    acc.w = fmaxf(acc.w + bb.w, 0.f);
    *(float4*)(g_o1 + (size_t)node * 128 + lane * 4) = acc;
}

// ---------------------------------------------------------------------------
__global__ __launch_bounds__(128) void k_gemm2(const float* __restrict__ W2, int N, int C) {
    __shared__ float Ws[128 * C_CAP];
    for (int i = threadIdx.x; i < 128 * C; i += blockDim.x) Ws[i] = W2[i];
    __syncthreads();
    int warp = threadIdx.x >> 5;
    int lane = threadIdx.x & 31;
    int n = blockIdx.x * 4 + warp;
    if (n >= N) return;
    const float* xr = g_o1 + (size_t)n * 128;
    float a0 = 0.f, a1 = 0.f;
    int c1 = lane + 32;
#pragma unroll 4
    for (int k = 0; k < 128; k++) {
        float xv = xr[k];
        a0 += xv * Ws[k * C + lane];
        a1 += xv * Ws[k * C + (c1 < C ? c1 : 0)];
    }
    g_h2[(size_t)n * C + lane] = a0;
    if (c1 < C) g_h2[(size_t)n * C + c1] = a1;
}

// ---------------------------------------------------------------------------
// Layer-2: warp-per-node gather (MLP-2) + self + bias + log_softmax -> out
// ---------------------------------------------------------------------------
__global__ __launch_bounds__(256) void k_agg2_gather(float* __restrict__ out,
                                                     const float* __restrict__ b2,
                                                     int N, int C) {
    int node = (blockIdx.x * blockDim.x + threadIdx.x) >> 5;
    int lane = threadIdx.x & 31;
    if (node >= N) return;
    int s = g_rs[node], e = s + g_cnt[node];
    float d = g_dinv[node];
    float dd = d * d;
    int c1 = lane + 32;
    bool has1 = c1 < C;
    const float* h0 = g_h2 + (size_t)node * C;
    float a0 = dd * h0[lane];
    float a1 = has1 ? dd * h0[c1] : 0.f;
    int t = s;
    for (; t + 2 <= e; t += 2) {
        uint2 p0 = g_epay[t], p1 = g_epay[t + 1];
        const float* hp0 = g_h2 + (size_t)p0.x * C;
        const float* hp1 = g_h2 + (size_t)p1.x * C;
        float n0 = __uint_as_float(p0.y), n1 = __uint_as_float(p1.y);
        a0 += n0 * hp0[lane] + n1 * hp1[lane];
        if (has1) a1 += n0 * hp0[c1] + n1 * hp1[c1];
    }
    for (; t < e; t++) {
        uint2 p = g_epay[t];
        float nr = __uint_as_float(p.y);
        const float* hp = g_h2 + (size_t)p.x * C;
        a0 += nr * hp[lane];
        if (has1) a1 += nr * hp[c1];
    }
    a0 += b2[lane];
    if (has1) a1 += b2[c1];
    const float NEG_INF = __int_as_float(0xff800000);
    float v1 = has1 ? a1 : NEG_INF;
    float m = fmaxf(a0, v1);
#pragma unroll
    for (int o = 16; o > 0; o >>= 1) m = fmaxf(m, __shfl_xor_sync(0xffffffffu, m, o));
    float sum = expf(a0 - m) + (has1 ? expf(a1 - m) : 0.f);
#pragma unroll
    for (int o = 16; o > 0; o >>= 1) sum += __shfl_xor_sync(0xffffffffu, sum, o);
    float l = logf(sum);
    float* z = out + (size_t)node * C;
    z[lane] = a0 - m - l;
    if (has1) z[c1] = a1 - m - l;
}

// ---------------------------------------------------------------------------
extern "C" void kernel_launch(void* const* d_in, const int* in_sizes, int n_in,
                              void* d_out, int out_size) {
    const float* feat = (const float*)d_in[0];
    const void*  ei   = d_in[1];
    const float* ew   = (const float*)d_in[2];
    const float* W1   = (const float*)d_in[3];
    const float* b1   = (const float*)d_in[4];
    const float* W2   = (const float*)d_in[5];
    const float* b2   = (const float*)d_in[6];
    float* out = (float*)d_out;

    int H   = in_sizes[4];
    int FIN = in_sizes[3] / H;
    int N   = in_sizes[0] / FIN;
    int C   = in_sizes[6];
    int E   = in_sizes[2];
    (void)n_in; (void)out_size;

    int nsb = (N + 1023) / 1024;   // scan blocks (<= 64)

    k_init_detect<<<(N + 255) / 256, 256>>>((const unsigned int*)ei, (long long)2 * E, N);
    k_deg_count<<<(E + 255) / 256, 256>>>(ei, ew, E);
    k_scan1<<<nsb, 1024>>>(N);
    k_scan2<<<nsb, 1024>>>(N);
    k_fill<<<(E + 255) / 256, 256>>>(ei, ew, E);

    k_prepB<<<(FIN * 128 + 255) / 256, 256>>>(W1, FIN);
    k_gemm1_mma<<<(N + 127) / 128, 256>>>(feat, N, FIN);

    k_agg1_gather<<<(N + 7) / 8, 256>>>(b1, N);
    k_gemm2<<<(N + 3) / 4, 128>>>(W2, N, C);
    k_agg2_gather<<<(N + 7) / 8, 256>>>(out, b2, N, C);
}